// round 1
// baseline (speedup 1.0000x reference)
#include <cuda_runtime.h>
#include <cstdint>

// ---------------------------------------------------------------------------
// SwinBasicBlock: out = 2 * (window_attention(LN(x)) + x), transposed BCHW.
// MLP branch in the reference is computed then DISCARDED -> we skip it.
//
// Shapes: B=8, C=256, H=W=128, WS=8, NH=8, hd=32, SHIFT=4
// Rows M = B*(H/8)*(W/8)*64 = 131072
// ---------------------------------------------------------------------------

#define Bdim 8
#define Cdim 256
#define Hdim 128
#define Wdim 128
#define NHEAD 8
#define HD 32
#define MROWS (131072)

// Scratch (device globals; no allocation APIs allowed)
__device__ float g_Y[MROWS * Cdim];          // 134 MB  LN+roll+partition output
__device__ float g_QKV[MROWS * 3 * Cdim];    // 403 MB  qkv
__device__ float g_O[MROWS * Cdim];          // 134 MB  attention output
__device__ float g_P[MROWS * Cdim];          // 134 MB  proj output

// ---------------------------------------------------------------------------
// K1: LayerNorm over C + cyclic shift (-4,-4) + window partition.
// x is (B,C,H,W); output Y is ((win*64+n), C) row-major.
// Block = (wtile=4, h=128, b=8), 256 threads. smem transpose for coalescing.
// ---------------------------------------------------------------------------
__global__ void k1_ln_roll_part(const float* __restrict__ x,
                                const float* __restrict__ gamma,
                                const float* __restrict__ beta,
                                float* __restrict__ Y) {
    __shared__ float tile[32][257];
    const int b  = blockIdx.z;
    const int h  = blockIdx.y;
    const int w0 = blockIdx.x * 32;
    const int t  = threadIdx.x;
    const int wl = t & 31;       // w lane
    const int co = t >> 5;       // channel offset 0..7

    const float* xb = x + (long)b * Cdim * Hdim * Wdim;

    // load 32 pixels x 256 channels, coalesced over w
    #pragma unroll
    for (int cb = 0; cb < Cdim; cb += 8) {
        const int c = cb + co;
        tile[wl][c] = xb[((long)c * Hdim + h) * Wdim + w0 + wl];
    }
    __syncthreads();

    // LayerNorm: 8 threads per pixel
    const int p   = t >> 3;
    const int sub = t & 7;
    float s = 0.f, ss = 0.f;
    #pragma unroll
    for (int c = sub; c < Cdim; c += 8) {
        const float v = tile[p][c];
        s += v; ss += v * v;
    }
    #pragma unroll
    for (int off = 4; off > 0; off >>= 1) {
        s  += __shfl_xor_sync(0xffffffffu, s,  off);
        ss += __shfl_xor_sync(0xffffffffu, ss, off);
    }
    const float mean = s * (1.f / Cdim);
    const float var  = ss * (1.f / Cdim) - mean * mean;
    const float inv  = rsqrtf(var + 1e-5f);
    #pragma unroll
    for (int c = sub; c < Cdim; c += 8) {
        tile[p][c] = (tile[p][c] - mean) * inv * gamma[c] + beta[c];
    }
    __syncthreads();

    // scatter to window layout with shift (-4,-4): dest (h-4, w-4) mod 128
    const int h2 = (h - 4) & 127;
    #pragma unroll 4
    for (int p2 = 0; p2 < 32; p2++) {
        const int w2 = (w0 + p2 - 4) & 127;
        const long row = (((long)b * 16 + (h2 >> 3)) * 16 + (w2 >> 3)) * 64
                         + (h2 & 7) * 8 + (w2 & 7);
        Y[row * Cdim + t] = tile[p2][t];
    }
}

// ---------------------------------------------------------------------------
// K2/K4: SGEMM C[M,N] = A[M,K] @ B[K,N] + bias.  Block tile 64x64, BK=16,
// 256 threads, 4x4 micro-tile per thread, float4 smem reads.
// ---------------------------------------------------------------------------
__global__ void sgemm_bias(const float* __restrict__ A,
                           const float* __restrict__ B,
                           const float* __restrict__ bias,
                           float* __restrict__ C,
                           int M, int N, int K) {
    __shared__ float As[16][68];   // A^T tile: [k][m], padded for conflicts/alignment
    __shared__ float Bs[16][64];   // [k][n]

    const int t  = threadIdx.x;
    const int bm = blockIdx.y * 64;
    const int bn = blockIdx.x * 64;
    const int tm = t >> 4;         // 0..15
    const int tn = t & 15;         // 0..15

    const int la_m = t >> 2;        // 0..63
    const int la_k = (t & 3) * 4;   // 0,4,8,12
    const int lb_k = t >> 4;        // 0..15
    const int lb_n = (t & 15) * 4;  // 0..60

    const float* Ap = A + (long)(bm + la_m) * K + la_k;
    const float* Bp = B + (long)lb_k * N + bn + lb_n;

    float acc[4][4] = {};

    for (int k0 = 0; k0 < K; k0 += 16) {
        const float4 av = *(const float4*)(Ap + k0);
        As[la_k + 0][la_m] = av.x;
        As[la_k + 1][la_m] = av.y;
        As[la_k + 2][la_m] = av.z;
        As[la_k + 3][la_m] = av.w;
        *(float4*)&Bs[lb_k][lb_n] = *(const float4*)(Bp + (long)k0 * N);
        __syncthreads();

        #pragma unroll
        for (int k = 0; k < 16; k++) {
            const float4 a = *(const float4*)&As[k][tm * 4];
            const float4 b = *(const float4*)&Bs[k][tn * 4];
            acc[0][0] += a.x * b.x; acc[0][1] += a.x * b.y; acc[0][2] += a.x * b.z; acc[0][3] += a.x * b.w;
            acc[1][0] += a.y * b.x; acc[1][1] += a.y * b.y; acc[1][2] += a.y * b.z; acc[1][3] += a.y * b.w;
            acc[2][0] += a.z * b.x; acc[2][1] += a.z * b.y; acc[2][2] += a.z * b.z; acc[2][3] += a.z * b.w;
            acc[3][0] += a.w * b.x; acc[3][1] += a.w * b.y; acc[3][2] += a.w * b.z; acc[3][3] += a.w * b.w;
        }
        __syncthreads();
    }

    const float4 bb = *(const float4*)&bias[bn + tn * 4];
    #pragma unroll
    for (int i = 0; i < 4; i++) {
        float4 o;
        o.x = acc[i][0] + bb.x;
        o.y = acc[i][1] + bb.y;
        o.z = acc[i][2] + bb.z;
        o.w = acc[i][3] + bb.w;
        *(float4*)&C[(long)(bm + tm * 4 + i) * N + bn + tn * 4] = o;
    }
}

// ---------------------------------------------------------------------------
// K3: per-(window, head) attention. N=64 tokens, hd=32.
// S = q k^T * scale, rowwise softmax, O = S v.
// 256 threads = 8 warps; warp w owns rows 8w..8w+7 end-to-end (no cross-warp
// dependency after the load sync).
// ---------------------------------------------------------------------------
__global__ void k3_attention(const float* __restrict__ QKV,
                             float* __restrict__ O) {
    __shared__ float qs[64][33];
    __shared__ float ks[64][33];
    __shared__ float vs[64][33];
    __shared__ float sm[64][65];

    const int head = blockIdx.x;
    const int win  = blockIdx.y;
    const int t    = threadIdx.x;
    const int lane = t & 31;
    const int w    = t >> 5;

    const long base = (long)win * 64 * 768 + head * 32;
    for (int n = w; n < 64; n += 8) {
        const long r = base + (long)n * 768;
        qs[n][lane] = QKV[r + lane];
        ks[n][lane] = QKV[r + 256 + lane];
        vs[n][lane] = QKV[r + 512 + lane];
    }
    __syncthreads();

    const float scale = 0.1767766952966369f;  // 32^-0.5

    #pragma unroll
    for (int rr = 0; rr < 8; rr++) {
        const int i = w * 8 + rr;
        float d0 = 0.f, d1 = 0.f;
        #pragma unroll
        for (int kk = 0; kk < 32; kk++) {
            const float qv = qs[i][kk];
            d0 += qv * ks[lane][kk];
            d1 += qv * ks[lane + 32][kk];
        }
        d0 *= scale; d1 *= scale;
        float m = fmaxf(d0, d1);
        #pragma unroll
        for (int off = 16; off > 0; off >>= 1)
            m = fmaxf(m, __shfl_xor_sync(0xffffffffu, m, off));
        const float e0 = __expf(d0 - m);
        const float e1 = __expf(d1 - m);
        float ssum = e0 + e1;
        #pragma unroll
        for (int off = 16; off > 0; off >>= 1)
            ssum += __shfl_xor_sync(0xffffffffu, ssum, off);
        const float r = 1.f / ssum;
        sm[i][lane]      = e0 * r;
        sm[i][lane + 32] = e1 * r;
    }
    __syncwarp();

    const long obase = (long)win * 64 * 256 + head * 32 + lane;
    #pragma unroll
    for (int rr = 0; rr < 8; rr++) {
        const int i = w * 8 + rr;
        float acc = 0.f;
        #pragma unroll
        for (int j = 0; j < 64; j++)
            acc += sm[i][j] * vs[j][lane];
        O[obase + (long)i * 256] = acc;
    }
}

// ---------------------------------------------------------------------------
// K5: window reverse + roll(+4,+4) + residual doubling + transpose to BCHW.
// out[b][c][h][w] = 2 * (P_at(h-4, w-4 mod 128 via window map)[c] + x[b][c][h][w])
// ---------------------------------------------------------------------------
__global__ void k5_epilogue(const float* __restrict__ P,
                            const float* __restrict__ x,
                            float* __restrict__ out) {
    __shared__ float tile[32][257];
    const int b  = blockIdx.z;
    const int h  = blockIdx.y;
    const int w0 = blockIdx.x * 32;
    const int t  = threadIdx.x;

    const int h2 = (h - 4) & 127;
    #pragma unroll 4
    for (int p2 = 0; p2 < 32; p2++) {
        const int w2 = (w0 + p2 - 4) & 127;
        const long row = (((long)b * 16 + (h2 >> 3)) * 16 + (w2 >> 3)) * 64
                         + (h2 & 7) * 8 + (w2 & 7);
        tile[p2][t] = P[row * Cdim + t];
    }
    __syncthreads();

    const int wl = t & 31;
    const int co = t >> 5;
    const long base = (long)b * Cdim * Hdim * Wdim;
    #pragma unroll
    for (int cb = 0; cb < Cdim; cb += 8) {
        const int c = cb + co;
        const long idx = base + ((long)c * Hdim + h) * Wdim + w0 + wl;
        out[idx] = 2.f * (tile[wl][c] + x[idx]);
    }
}

// ---------------------------------------------------------------------------
extern "C" void kernel_launch(void* const* d_in, const int* in_sizes, int n_in,
                              void* d_out, int out_size) {
    const float* x      = (const float*)d_in[0];
    const float* n1g    = (const float*)d_in[1];
    const float* n1b    = (const float*)d_in[2];
    const float* w_qkv  = (const float*)d_in[3];
    const float* b_qkv  = (const float*)d_in[4];
    const float* w_proj = (const float*)d_in[5];
    const float* b_proj = (const float*)d_in[6];
    // inputs 7..12 (norm2_g/b, w1, b1, w2, b2) feed the discarded MLP branch.
    float* out = (float*)d_out;

    float *Y, *QKV, *Obuf, *P;
    cudaGetSymbolAddress((void**)&Y,    g_Y);
    cudaGetSymbolAddress((void**)&QKV,  g_QKV);
    cudaGetSymbolAddress((void**)&Obuf, g_O);
    cudaGetSymbolAddress((void**)&P,    g_P);

    // K1: LN + shift + window partition
    k1_ln_roll_part<<<dim3(4, 128, 8), 256>>>(x, n1g, n1b, Y);

    // K2: QKV GEMM  (131072 x 768) = Y(131072x256) @ w_qkv(256x768) + b_qkv
    sgemm_bias<<<dim3(768 / 64, MROWS / 64), 256>>>(Y, w_qkv, b_qkv, QKV,
                                                    MROWS, 768, 256);

    // K3: windowed attention (2048 windows x 8 heads)
    k3_attention<<<dim3(NHEAD, 2048), 256>>>(QKV, Obuf);

    // K4: proj GEMM  (131072 x 256) = O @ w_proj + b_proj
    sgemm_bias<<<dim3(256 / 64, MROWS / 64), 256>>>(Obuf, w_proj, b_proj, P,
                                                    MROWS, 256, 256);

    // K5: window reverse + unshift + 2*(attn + x), transpose back to BCHW
    k5_epilogue<<<dim3(4, 128, 8), 256>>>(P, x, out);
}

// round 2
// speedup vs baseline: 1.8824x; 1.8824x over previous
#include <cuda_runtime.h>
#include <cstdint>

// ---------------------------------------------------------------------------
// SwinBasicBlock: out = 2 * (window_attention(LN(x)) + x), transposed BCHW.
// MLP branch in the reference is computed then DISCARDED -> we skip it.
//
// Shapes: B=8, C=256, H=W=128, WS=8, NH=8, hd=32, SHIFT=4
// Rows M = B*(H/8)*(W/8)*64 = 131072
// ---------------------------------------------------------------------------

#define Bdim 8
#define Cdim 256
#define Hdim 128
#define Wdim 128
#define NHEAD 8
#define HD 32
#define MROWS (131072)

// Scratch (device globals; no allocation APIs allowed)
__device__ float g_Y[MROWS * Cdim];          // 134 MB  LN+roll+partition output
__device__ float g_QKV[MROWS * 3 * Cdim];    // 403 MB  qkv
__device__ float g_O[MROWS * Cdim];          // 134 MB  attention output
__device__ float g_P[MROWS * Cdim];          // 134 MB  proj output

// ---------------------------------------------------------------------------
// K1: LayerNorm over C + cyclic shift (-4,-4) + window partition.
// ---------------------------------------------------------------------------
__global__ void k1_ln_roll_part(const float* __restrict__ x,
                                const float* __restrict__ gamma,
                                const float* __restrict__ beta,
                                float* __restrict__ Y) {
    __shared__ float tile[32][257];
    const int b  = blockIdx.z;
    const int h  = blockIdx.y;
    const int w0 = blockIdx.x * 32;
    const int t  = threadIdx.x;
    const int wl = t & 31;
    const int co = t >> 5;

    const float* xb = x + (long)b * Cdim * Hdim * Wdim;

    #pragma unroll
    for (int cb = 0; cb < Cdim; cb += 8) {
        const int c = cb + co;
        tile[wl][c] = xb[((long)c * Hdim + h) * Wdim + w0 + wl];
    }
    __syncthreads();

    const int p   = t >> 3;
    const int sub = t & 7;
    float s = 0.f, ss = 0.f;
    #pragma unroll
    for (int c = sub; c < Cdim; c += 8) {
        const float v = tile[p][c];
        s += v; ss += v * v;
    }
    #pragma unroll
    for (int off = 4; off > 0; off >>= 1) {
        s  += __shfl_xor_sync(0xffffffffu, s,  off);
        ss += __shfl_xor_sync(0xffffffffu, ss, off);
    }
    const float mean = s * (1.f / Cdim);
    const float var  = ss * (1.f / Cdim) - mean * mean;
    const float inv  = rsqrtf(var + 1e-5f);
    #pragma unroll
    for (int c = sub; c < Cdim; c += 8) {
        tile[p][c] = (tile[p][c] - mean) * inv * gamma[c] + beta[c];
    }
    __syncthreads();

    const int h2 = (h - 4) & 127;
    #pragma unroll 4
    for (int p2 = 0; p2 < 32; p2++) {
        const int w2 = (w0 + p2 - 4) & 127;
        const long row = (((long)b * 16 + (h2 >> 3)) * 16 + (w2 >> 3)) * 64
                         + (h2 & 7) * 8 + (w2 & 7);
        Y[row * Cdim + t] = tile[p2][t];
    }
}

// ---------------------------------------------------------------------------
// TF32 tensor-core GEMM: C[M,N] = A[M,K] @ B[K,N] + bias.
// Block tile 128x128, BK=16, 256 threads (8 warps), warp tile 64x32.
// mma.sync.aligned.m16n8k8.row.col.f32.tf32.tf32.f32
// ---------------------------------------------------------------------------
#define BM 128
#define BN 128
#define BKt 16
#define A_PITCH 20
#define B_PITCH 132

__device__ __forceinline__ uint32_t f2tf32(float f) {
    uint32_t r;
    asm("cvt.rna.tf32.f32 %0, %1;" : "=r"(r) : "f"(f));
    return r;
}

__device__ __forceinline__ void mma_tf32(float c[4], uint32_t a0, uint32_t a1,
                                         uint32_t a2, uint32_t a3,
                                         uint32_t b0, uint32_t b1) {
    asm volatile(
        "mma.sync.aligned.m16n8k8.row.col.f32.tf32.tf32.f32 "
        "{%0,%1,%2,%3}, {%4,%5,%6,%7}, {%8,%9}, {%0,%1,%2,%3};\n"
        : "+f"(c[0]), "+f"(c[1]), "+f"(c[2]), "+f"(c[3])
        : "r"(a0), "r"(a1), "r"(a2), "r"(a3), "r"(b0), "r"(b1));
}

__global__ __launch_bounds__(256, 2)
void tf32_gemm_bias(const float* __restrict__ A,
                    const float* __restrict__ B,
                    const float* __restrict__ bias,
                    float* __restrict__ C,
                    int M, int N, int K) {
    __shared__ uint32_t As[BM * A_PITCH];   // [m][k] pitch 20 (conflict-free frags)
    __shared__ uint32_t Bs[BKt * B_PITCH];  // [k][n] pitch 132

    const int t    = threadIdx.x;
    const int warp = t >> 5;
    const int lane = t & 31;
    const int gid  = lane >> 2;   // group id 0..7
    const int tig  = lane & 3;    // thread-in-group 0..3

    const int wm = (warp >> 2) * 64;  // warp m offset: 0/64
    const int wn = (warp & 3) * 32;   // warp n offset: 0/32/64/96

    const int bm = blockIdx.y * BM;
    const int bn = blockIdx.x * BN;

    // global->smem load mapping
    const int ar = t >> 2;        // 0..63
    const int ac = (t & 3) * 4;   // 0,4,8,12
    const int br = t >> 5;        // 0..7
    const int bc = (t & 31) * 4;  // 0..124

    const float* Ap0 = A + (long)(bm + ar) * K + ac;
    const float* Ap1 = A + (long)(bm + ar + 64) * K + ac;
    const float* Bp0 = B + (long)br * N + bn + bc;
    const float* Bp1 = B + (long)(br + 8) * N + bn + bc;

    float acc[4][4][4];
    #pragma unroll
    for (int i = 0; i < 4; i++)
        #pragma unroll
        for (int j = 0; j < 4; j++)
            #pragma unroll
            for (int r = 0; r < 4; r++)
                acc[i][j][r] = 0.f;

    float4 aR0, aR1, bR0, bR1;
    // prefetch tile 0
    aR0 = *(const float4*)(Ap0);
    aR1 = *(const float4*)(Ap1);
    bR0 = *(const float4*)(Bp0);
    bR1 = *(const float4*)(Bp1);

    const int KT = K / BKt;
    for (int kt = 0; kt < KT; kt++) {
        // store current tile (tf32-rounded)
        {
            uint32_t* a0p = &As[ar * A_PITCH + ac];
            a0p[0] = f2tf32(aR0.x); a0p[1] = f2tf32(aR0.y);
            a0p[2] = f2tf32(aR0.z); a0p[3] = f2tf32(aR0.w);
            uint32_t* a1p = &As[(ar + 64) * A_PITCH + ac];
            a1p[0] = f2tf32(aR1.x); a1p[1] = f2tf32(aR1.y);
            a1p[2] = f2tf32(aR1.z); a1p[3] = f2tf32(aR1.w);
            uint32_t* b0p = &Bs[br * B_PITCH + bc];
            b0p[0] = f2tf32(bR0.x); b0p[1] = f2tf32(bR0.y);
            b0p[2] = f2tf32(bR0.z); b0p[3] = f2tf32(bR0.w);
            uint32_t* b1p = &Bs[(br + 8) * B_PITCH + bc];
            b1p[0] = f2tf32(bR1.x); b1p[1] = f2tf32(bR1.y);
            b1p[2] = f2tf32(bR1.z); b1p[3] = f2tf32(bR1.w);
        }
        __syncthreads();

        // prefetch next tile
        if (kt + 1 < KT) {
            const int k0 = (kt + 1) * BKt;
            aR0 = *(const float4*)(Ap0 + k0);
            aR1 = *(const float4*)(Ap1 + k0);
            bR0 = *(const float4*)(Bp0 + (long)k0 * N);
            bR1 = *(const float4*)(Bp1 + (long)k0 * N);
        }

        // compute: 2 k8 steps
        #pragma unroll
        for (int ks = 0; ks < BKt; ks += 8) {
            uint32_t af[4][4];
            #pragma unroll
            for (int mt = 0; mt < 4; mt++) {
                const int m = wm + mt * 16 + gid;
                af[mt][0] = As[m * A_PITCH + ks + tig];
                af[mt][1] = As[(m + 8) * A_PITCH + ks + tig];
                af[mt][2] = As[m * A_PITCH + ks + tig + 4];
                af[mt][3] = As[(m + 8) * A_PITCH + ks + tig + 4];
            }
            uint32_t bf[4][2];
            #pragma unroll
            for (int nt = 0; nt < 4; nt++) {
                const int n = wn + nt * 8 + gid;
                bf[nt][0] = Bs[(ks + tig) * B_PITCH + n];
                bf[nt][1] = Bs[(ks + tig + 4) * B_PITCH + n];
            }
            #pragma unroll
            for (int mt = 0; mt < 4; mt++)
                #pragma unroll
                for (int nt = 0; nt < 4; nt++)
                    mma_tf32(acc[mt][nt], af[mt][0], af[mt][1], af[mt][2],
                             af[mt][3], bf[nt][0], bf[nt][1]);
        }
        __syncthreads();
    }

    // epilogue: bias + store (float2 per c-pair)
    #pragma unroll
    for (int nt = 0; nt < 4; nt++) {
        const int col = bn + wn + nt * 8 + 2 * tig;
        const float2 bb = *(const float2*)&bias[col];
        #pragma unroll
        for (int mt = 0; mt < 4; mt++) {
            const int row = bm + wm + mt * 16 + gid;
            float2 o0, o1;
            o0.x = acc[mt][nt][0] + bb.x;
            o0.y = acc[mt][nt][1] + bb.y;
            o1.x = acc[mt][nt][2] + bb.x;
            o1.y = acc[mt][nt][3] + bb.y;
            *(float2*)&C[(long)row * N + col]       = o0;
            *(float2*)&C[(long)(row + 8) * N + col] = o1;
        }
    }
}

// ---------------------------------------------------------------------------
// K3: per-(window, head) attention. N=64 tokens, hd=32. (unchanged)
// ---------------------------------------------------------------------------
__global__ void k3_attention(const float* __restrict__ QKV,
                             float* __restrict__ O) {
    __shared__ float qs[64][33];
    __shared__ float ks[64][33];
    __shared__ float vs[64][33];
    __shared__ float sm[64][65];

    const int head = blockIdx.x;
    const int win  = blockIdx.y;
    const int t    = threadIdx.x;
    const int lane = t & 31;
    const int w    = t >> 5;

    const long base = (long)win * 64 * 768 + head * 32;
    for (int n = w; n < 64; n += 8) {
        const long r = base + (long)n * 768;
        qs[n][lane] = QKV[r + lane];
        ks[n][lane] = QKV[r + 256 + lane];
        vs[n][lane] = QKV[r + 512 + lane];
    }
    __syncthreads();

    const float scale = 0.1767766952966369f;  // 32^-0.5

    #pragma unroll
    for (int rr = 0; rr < 8; rr++) {
        const int i = w * 8 + rr;
        float d0 = 0.f, d1 = 0.f;
        #pragma unroll
        for (int kk = 0; kk < 32; kk++) {
            const float qv = qs[i][kk];
            d0 += qv * ks[lane][kk];
            d1 += qv * ks[lane + 32][kk];
        }
        d0 *= scale; d1 *= scale;
        float m = fmaxf(d0, d1);
        #pragma unroll
        for (int off = 16; off > 0; off >>= 1)
            m = fmaxf(m, __shfl_xor_sync(0xffffffffu, m, off));
        const float e0 = __expf(d0 - m);
        const float e1 = __expf(d1 - m);
        float ssum = e0 + e1;
        #pragma unroll
        for (int off = 16; off > 0; off >>= 1)
            ssum += __shfl_xor_sync(0xffffffffu, ssum, off);
        const float r = 1.f / ssum;
        sm[i][lane]      = e0 * r;
        sm[i][lane + 32] = e1 * r;
    }
    __syncwarp();

    const long obase = (long)win * 64 * 256 + head * 32 + lane;
    #pragma unroll
    for (int rr = 0; rr < 8; rr++) {
        const int i = w * 8 + rr;
        float acc = 0.f;
        #pragma unroll
        for (int j = 0; j < 64; j++)
            acc += sm[i][j] * vs[j][lane];
        O[obase + (long)i * 256] = acc;
    }
}

// ---------------------------------------------------------------------------
// K5: window reverse + roll(+4,+4) + residual doubling + transpose to BCHW.
// ---------------------------------------------------------------------------
__global__ void k5_epilogue(const float* __restrict__ P,
                            const float* __restrict__ x,
                            float* __restrict__ out) {
    __shared__ float tile[32][257];
    const int b  = blockIdx.z;
    const int h  = blockIdx.y;
    const int w0 = blockIdx.x * 32;
    const int t  = threadIdx.x;

    const int h2 = (h - 4) & 127;
    #pragma unroll 4
    for (int p2 = 0; p2 < 32; p2++) {
        const int w2 = (w0 + p2 - 4) & 127;
        const long row = (((long)b * 16 + (h2 >> 3)) * 16 + (w2 >> 3)) * 64
                         + (h2 & 7) * 8 + (w2 & 7);
        tile[p2][t] = P[row * Cdim + t];
    }
    __syncthreads();

    const int wl = t & 31;
    const int co = t >> 5;
    const long base = (long)b * Cdim * Hdim * Wdim;
    #pragma unroll
    for (int cb = 0; cb < Cdim; cb += 8) {
        const int c = cb + co;
        const long idx = base + ((long)c * Hdim + h) * Wdim + w0 + wl;
        out[idx] = 2.f * (tile[wl][c] + x[idx]);
    }
}

// ---------------------------------------------------------------------------
extern "C" void kernel_launch(void* const* d_in, const int* in_sizes, int n_in,
                              void* d_out, int out_size) {
    const float* x      = (const float*)d_in[0];
    const float* n1g    = (const float*)d_in[1];
    const float* n1b    = (const float*)d_in[2];
    const float* w_qkv  = (const float*)d_in[3];
    const float* b_qkv  = (const float*)d_in[4];
    const float* w_proj = (const float*)d_in[5];
    const float* b_proj = (const float*)d_in[6];
    float* out = (float*)d_out;

    float *Y, *QKV, *Obuf, *P;
    cudaGetSymbolAddress((void**)&Y,    g_Y);
    cudaGetSymbolAddress((void**)&QKV,  g_QKV);
    cudaGetSymbolAddress((void**)&Obuf, g_O);
    cudaGetSymbolAddress((void**)&P,    g_P);

    // K1: LN + shift + window partition
    k1_ln_roll_part<<<dim3(4, 128, 8), 256>>>(x, n1g, n1b, Y);

    // K2: QKV GEMM (TF32 tensor cores)
    tf32_gemm_bias<<<dim3(768 / BN, MROWS / BM), 256>>>(Y, w_qkv, b_qkv, QKV,
                                                        MROWS, 768, 256);

    // K3: windowed attention (2048 windows x 8 heads)
    k3_attention<<<dim3(NHEAD, 2048), 256>>>(QKV, Obuf);

    // K4: proj GEMM (TF32 tensor cores)
    tf32_gemm_bias<<<dim3(256 / BN, MROWS / BM), 256>>>(Obuf, w_proj, b_proj, P,
                                                        MROWS, 256, 256);

    // K5: window reverse + unshift + 2*(attn + x), transpose back to BCHW
    k5_epilogue<<<dim3(4, 128, 8), 256>>>(P, x, out);
}

// round 3
// speedup vs baseline: 4.2445x; 2.2548x over previous
#include <cuda_runtime.h>
#include <cuda_bf16.h>
#include <cstdint>

// ---------------------------------------------------------------------------
// SwinBasicBlock: out = 2 * (window_attention(LN(x)) + x), BCHW.
// MLP branch is dead code in the reference -> skipped.
// B=8, C=256, H=W=128, WS=8, NH=8, hd=32, SHIFT=4, M = 131072 rows.
// ---------------------------------------------------------------------------

#define Cdim 256
#define Hdim 128
#define Wdim 128
#define MROWS 131072

// Scratch (device globals; allocation APIs forbidden)
__device__ __nv_bfloat16 g_Y[MROWS * Cdim];       // LN output, bf16
__device__ __nv_bfloat16 g_QKV[MROWS * 3 * Cdim]; // qkv, bf16
__device__ __nv_bfloat16 g_O[MROWS * Cdim];       // attn out, bf16
__device__ float         g_P[MROWS * Cdim];       // proj out, fp32
__device__ __nv_bfloat16 g_WTq[768 * 256];        // w_qkv^T  [n][k]
__device__ __nv_bfloat16 g_WTp[256 * 256];        // w_proj^T [n][k]

// ------------------------------ PTX helpers --------------------------------
__device__ __forceinline__ void cp16(uint32_t dst, const void* src) {
    asm volatile("cp.async.cg.shared.global [%0], [%1], 16;\n"
                 :: "r"(dst), "l"(src));
}
__device__ __forceinline__ void cp_commit() {
    asm volatile("cp.async.commit_group;\n");
}
template <int N> __device__ __forceinline__ void cp_wait() {
    asm volatile("cp.async.wait_group %0;\n" :: "n"(N));
}
__device__ __forceinline__ void ldsm_x4(uint32_t r[4], uint32_t addr) {
    asm volatile("ldmatrix.sync.aligned.m8n8.x4.shared.b16 {%0,%1,%2,%3}, [%4];\n"
                 : "=r"(r[0]), "=r"(r[1]), "=r"(r[2]), "=r"(r[3]) : "r"(addr));
}
__device__ __forceinline__ void ldsm_x4_t(uint32_t r[4], uint32_t addr) {
    asm volatile("ldmatrix.sync.aligned.m8n8.x4.trans.shared.b16 {%0,%1,%2,%3}, [%4];\n"
                 : "=r"(r[0]), "=r"(r[1]), "=r"(r[2]), "=r"(r[3]) : "r"(addr));
}
__device__ __forceinline__ void mma_bf16(float c[4], const uint32_t a[4],
                                         uint32_t b0, uint32_t b1) {
    asm volatile(
        "mma.sync.aligned.m16n8k16.row.col.f32.bf16.bf16.f32 "
        "{%0,%1,%2,%3},{%4,%5,%6,%7},{%8,%9},{%0,%1,%2,%3};\n"
        : "+f"(c[0]), "+f"(c[1]), "+f"(c[2]), "+f"(c[3])
        : "r"(a[0]), "r"(a[1]), "r"(a[2]), "r"(a[3]), "r"(b0), "r"(b1));
}
__device__ __forceinline__ uint32_t packbf(float lo, float hi) {
    uint32_t r;
    asm("cvt.rn.bf16x2.f32 %0, %1, %2;\n" : "=r"(r) : "f"(hi), "f"(lo));
    return r;
}
__device__ __forceinline__ uint32_t s2u(const void* p) {
    return (uint32_t)__cvta_generic_to_shared(p);
}

// ---------------------------------------------------------------------------
// W0: transpose weights to [N][K] bf16.
// ---------------------------------------------------------------------------
__global__ void wconv(const float* __restrict__ wq, const float* __restrict__ wp) {
    const int idx = blockIdx.x * 256 + threadIdx.x;   // 768*256 threads
    const int n = idx >> 8, k = idx & 255;
    g_WTq[idx] = __float2bfloat16(wq[k * 768 + n]);
    if (n < 256) g_WTp[idx] = __float2bfloat16(wp[k * 256 + n]);
}

// ---------------------------------------------------------------------------
// K1: LayerNorm over C + cyclic shift (-4,-4) + window partition -> bf16 Y.
// ---------------------------------------------------------------------------
__global__ void k1_ln_roll_part(const float* __restrict__ x,
                                const float* __restrict__ gamma,
                                const float* __restrict__ beta,
                                __nv_bfloat16* __restrict__ Y) {
    __shared__ float tile[32][257];
    const int b  = blockIdx.z;
    const int h  = blockIdx.y;
    const int w0 = blockIdx.x * 32;
    const int t  = threadIdx.x;
    const int wl = t & 31;
    const int co = t >> 5;

    const float* xb = x + (long)b * Cdim * Hdim * Wdim;
    #pragma unroll
    for (int cb = 0; cb < Cdim; cb += 8) {
        const int c = cb + co;
        tile[wl][c] = xb[((long)c * Hdim + h) * Wdim + w0 + wl];
    }
    __syncthreads();

    const int p = t >> 3, sub = t & 7;
    float s = 0.f, ss = 0.f;
    #pragma unroll
    for (int c = sub; c < Cdim; c += 8) {
        const float v = tile[p][c];
        s += v; ss += v * v;
    }
    #pragma unroll
    for (int off = 4; off > 0; off >>= 1) {
        s  += __shfl_xor_sync(0xffffffffu, s,  off);
        ss += __shfl_xor_sync(0xffffffffu, ss, off);
    }
    const float mean = s * (1.f / Cdim);
    const float var  = ss * (1.f / Cdim) - mean * mean;
    const float inv  = rsqrtf(var + 1e-5f);
    #pragma unroll
    for (int c = sub; c < Cdim; c += 8)
        tile[p][c] = (tile[p][c] - mean) * inv * gamma[c] + beta[c];
    __syncthreads();

    const int h2 = (h - 4) & 127;
    #pragma unroll 4
    for (int p2 = 0; p2 < 32; p2++) {
        const int w2 = (w0 + p2 - 4) & 127;
        const long row = (((long)b * 16 + (h2 >> 3)) * 16 + (w2 >> 3)) * 64
                         + (h2 & 7) * 8 + (w2 & 7);
        Y[row * Cdim + t] = __float2bfloat16(tile[p2][t]);
    }
}

// ---------------------------------------------------------------------------
// bf16 tensor-core GEMM: C[M,N] = A[M,K=256] @ WT[N][K]^T + bias
// Block 128x128, BK=32, 8 warps, warp tile 64x32, cp.async double buffer,
// ldmatrix fragments, pitch-40-half smem rows (conflict-free LDSM).
// ---------------------------------------------------------------------------
#define GP 40   // smem row pitch in halves

template <bool OUT_BF16>
__global__ __launch_bounds__(256)
void bf16_gemm(const __nv_bfloat16* __restrict__ A,
               const __nv_bfloat16* __restrict__ WT,
               const float* __restrict__ bias,
               void* __restrict__ Cv, int N) {
    __shared__ __nv_bfloat16 As[2][128 * GP];
    __shared__ __nv_bfloat16 Bs[2][128 * GP];
    const int K = 256;

    const int t    = threadIdx.x;
    const int warp = t >> 5;
    const int lane = t & 31;
    const int gid  = lane >> 2;
    const int tig  = lane & 3;
    const int wm   = (warp >> 2) * 64;
    const int wn   = (warp & 3) * 32;
    const int bm   = blockIdx.y * 128;
    const int bn   = blockIdx.x * 128;

    const uint32_t asb = s2u(&As[0][0]);
    const uint32_t bsb = s2u(&Bs[0][0]);

    auto loadStage = [&](int st, int k0) {
        #pragma unroll
        for (int i = 0; i < 2; i++) {
            const int ci  = t + i * 256;          // 0..511
            const int row = ci >> 2;
            const int kc  = (ci & 3) * 8;
            cp16(asb + (st * 128 * GP + row * GP + kc) * 2,
                 A + (long)(bm + row) * K + k0 + kc);
            cp16(bsb + (st * 128 * GP + row * GP + kc) * 2,
                 WT + (long)(bn + row) * K + k0 + kc);
        }
        cp_commit();
    };

    float acc[4][4][4];
    #pragma unroll
    for (int i = 0; i < 4; i++)
        #pragma unroll
        for (int j = 0; j < 4; j++)
            #pragma unroll
            for (int r = 0; r < 4; r++) acc[i][j][r] = 0.f;

    loadStage(0, 0);

    const int r16  = lane & 15;
    const int hsel = (lane >> 4) << 3;

    #pragma unroll 1
    for (int kt = 0; kt < 8; kt++) {
        cp_wait<0>();
        __syncthreads();
        if (kt + 1 < 8) loadStage((kt + 1) & 1, (kt + 1) * 32);

        const int st = kt & 1;
        #pragma unroll
        for (int ks = 0; ks < 2; ks++) {
            uint32_t af[4][4];
            #pragma unroll
            for (int mt = 0; mt < 4; mt++)
                ldsm_x4(af[mt], asb + (st * 128 * GP
                        + (wm + mt * 16 + r16) * GP + ks * 16 + hsel) * 2);
            #pragma unroll
            for (int np = 0; np < 2; np++) {
                // 2 n-tiles per x4: lanes 0-7 (n0..7,k0) 8-15 (n0..7,k8)
                //                   16-23 (n8..15,k0) 24-31 (n8..15,k8)
                const int sel = lane >> 3, l8 = lane & 7;
                const int brow = wn + np * 16 + ((sel & 2) ? 8 : 0) + l8;
                const int bcol = ks * 16 + ((sel & 1) ? 8 : 0);
                uint32_t bf[4];
                ldsm_x4(bf, bsb + (st * 128 * GP + brow * GP + bcol) * 2);
                #pragma unroll
                for (int mt = 0; mt < 4; mt++) {
                    mma_bf16(acc[mt][np * 2],     af[mt], bf[0], bf[1]);
                    mma_bf16(acc[mt][np * 2 + 1], af[mt], bf[2], bf[3]);
                }
            }
        }
        __syncthreads();
    }

    #pragma unroll
    for (int nt = 0; nt < 4; nt++) {
        const int col = bn + wn + nt * 8 + 2 * tig;
        const float b0 = bias[col], b1 = bias[col + 1];
        #pragma unroll
        for (int mt = 0; mt < 4; mt++) {
            const long row = bm + wm + mt * 16 + gid;
            if (OUT_BF16) {
                __nv_bfloat16* Cb = (__nv_bfloat16*)Cv;
                *(uint32_t*)&Cb[row * N + col] =
                    packbf(acc[mt][nt][0] + b0, acc[mt][nt][1] + b1);
                *(uint32_t*)&Cb[(row + 8) * N + col] =
                    packbf(acc[mt][nt][2] + b0, acc[mt][nt][3] + b1);
            } else {
                float* Cf = (float*)Cv;
                *(float2*)&Cf[row * N + col] =
                    make_float2(acc[mt][nt][0] + b0, acc[mt][nt][1] + b1);
                *(float2*)&Cf[(row + 8) * N + col] =
                    make_float2(acc[mt][nt][2] + b0, acc[mt][nt][3] + b1);
            }
        }
    }
}

// ---------------------------------------------------------------------------
// K3: tensor-core windowed attention. 1 window/block, warp-per-head (8 warps).
// S = QK^T (mma), register softmax, O = P V (S-accum repacked as A operand).
// Smem: Q/K/V staged per head at pitch 40 halves. 122880 B dynamic.
// ---------------------------------------------------------------------------
#define AP 40
#define HTILE (64 * AP)   // halves per (matrix, head)

__global__ __launch_bounds__(256)
void k3_attention(const __nv_bfloat16* __restrict__ QKV,
                  __nv_bfloat16* __restrict__ O) {
    extern __shared__ __nv_bfloat16 smem[];
    const int win  = blockIdx.x;
    const int t    = threadIdx.x;
    const int head = t >> 5;
    const int lane = t & 31;
    const int gid  = lane >> 2;
    const int tig  = lane & 3;

    const uint32_t sb = s2u(smem);

    // cooperative load of the whole window slice (64 x 768 bf16 = 96KB)
    {
        const __nv_bfloat16* src = QKV + (long)win * 64 * 768;
        #pragma unroll
        for (int i = 0; i < 24; i++) {
            const int ci    = i * 256 + t;          // 0..6143 (16B chunks)
            const int token = ci / 96;
            const int c2    = ci % 96;
            const int qkv   = c2 >> 5;
            const int rest  = c2 & 31;
            const int hh    = rest >> 2;
            const int kc    = (rest & 3) * 8;
            cp16(sb + ((qkv * 8 + hh) * HTILE + token * AP + kc) * 2,
                 src + (long)token * 768 + qkv * 256 + hh * 32 + kc);
        }
        cp_commit();
        cp_wait<0>();
        __syncthreads();
    }

    const uint32_t qb = sb + (head * HTILE) * 2;
    const uint32_t kb = sb + ((8 + head) * HTILE) * 2;
    const uint32_t vb = sb + ((16 + head) * HTILE) * 2;

    const int r16  = lane & 15;
    const int hsel = (lane >> 4) << 3;
    const int sel  = lane >> 3, l8 = lane & 7;

    // ---- S = Q K^T (64x64), fp32 accum
    float sc[4][8][4];
    #pragma unroll
    for (int mt = 0; mt < 4; mt++)
        #pragma unroll
        for (int nt = 0; nt < 8; nt++)
            #pragma unroll
            for (int r = 0; r < 4; r++) sc[mt][nt][r] = 0.f;

    #pragma unroll
    for (int ks = 0; ks < 2; ks++) {
        uint32_t af[4][4];
        #pragma unroll
        for (int mt = 0; mt < 4; mt++)
            ldsm_x4(af[mt], qb + ((mt * 16 + r16) * AP + ks * 16 + hsel) * 2);
        #pragma unroll
        for (int np = 0; np < 4; np++) {
            const int brow = np * 16 + ((sel & 2) ? 8 : 0) + l8;
            const int bcol = ks * 16 + ((sel & 1) ? 8 : 0);
            uint32_t bf[4];
            ldsm_x4(bf, kb + (brow * AP + bcol) * 2);
            #pragma unroll
            for (int mt = 0; mt < 4; mt++) {
                mma_bf16(sc[mt][np * 2],     af[mt], bf[0], bf[1]);
                mma_bf16(sc[mt][np * 2 + 1], af[mt], bf[2], bf[3]);
            }
        }
    }

    // ---- softmax over rows (scale folded into exp argument)
    const float scale = 0.17677669529663689f;
    float ilo[4], ihi[4];
    #pragma unroll
    for (int mt = 0; mt < 4; mt++) {
        float mlo = -1e30f, mhi = -1e30f;
        #pragma unroll
        for (int nt = 0; nt < 8; nt++) {
            mlo = fmaxf(mlo, fmaxf(sc[mt][nt][0], sc[mt][nt][1]));
            mhi = fmaxf(mhi, fmaxf(sc[mt][nt][2], sc[mt][nt][3]));
        }
        mlo = fmaxf(mlo, __shfl_xor_sync(0xffffffffu, mlo, 1));
        mlo = fmaxf(mlo, __shfl_xor_sync(0xffffffffu, mlo, 2));
        mhi = fmaxf(mhi, __shfl_xor_sync(0xffffffffu, mhi, 1));
        mhi = fmaxf(mhi, __shfl_xor_sync(0xffffffffu, mhi, 2));
        float slo = 0.f, shi = 0.f;
        #pragma unroll
        for (int nt = 0; nt < 8; nt++) {
            sc[mt][nt][0] = __expf(scale * (sc[mt][nt][0] - mlo));
            sc[mt][nt][1] = __expf(scale * (sc[mt][nt][1] - mlo));
            sc[mt][nt][2] = __expf(scale * (sc[mt][nt][2] - mhi));
            sc[mt][nt][3] = __expf(scale * (sc[mt][nt][3] - mhi));
            slo += sc[mt][nt][0] + sc[mt][nt][1];
            shi += sc[mt][nt][2] + sc[mt][nt][3];
        }
        slo += __shfl_xor_sync(0xffffffffu, slo, 1);
        slo += __shfl_xor_sync(0xffffffffu, slo, 2);
        shi += __shfl_xor_sync(0xffffffffu, shi, 1);
        shi += __shfl_xor_sync(0xffffffffu, shi, 2);
        ilo[mt] = 1.f / slo;
        ihi[mt] = 1.f / shi;
    }

    // ---- O = P V (64x32): P packed from S accum (normalized), V via trans
    float oc[4][4][4];
    #pragma unroll
    for (int mt = 0; mt < 4; mt++)
        #pragma unroll
        for (int nt = 0; nt < 4; nt++)
            #pragma unroll
            for (int r = 0; r < 4; r++) oc[mt][nt][r] = 0.f;

    #pragma unroll
    for (int ks = 0; ks < 4; ks++) {   // token chunks of 16
        uint32_t pa[4][4];
        #pragma unroll
        for (int mt = 0; mt < 4; mt++) {
            pa[mt][0] = packbf(sc[mt][2 * ks][0] * ilo[mt], sc[mt][2 * ks][1] * ilo[mt]);
            pa[mt][1] = packbf(sc[mt][2 * ks][2] * ihi[mt], sc[mt][2 * ks][3] * ihi[mt]);
            pa[mt][2] = packbf(sc[mt][2 * ks + 1][0] * ilo[mt], sc[mt][2 * ks + 1][1] * ilo[mt]);
            pa[mt][3] = packbf(sc[mt][2 * ks + 1][2] * ihi[mt], sc[mt][2 * ks + 1][3] * ihi[mt]);
        }
        #pragma unroll
        for (int dp = 0; dp < 2; dp++) {  // dim chunks of 16
            const int vrow = ks * 16 + ((sel & 1) ? 8 : 0) + l8;
            const int vcol = dp * 16 + ((sel & 2) ? 8 : 0);
            uint32_t vf[4];
            ldsm_x4_t(vf, vb + (vrow * AP + vcol) * 2);
            #pragma unroll
            for (int mt = 0; mt < 4; mt++) {
                mma_bf16(oc[mt][dp * 2],     pa[mt], vf[0], vf[1]);
                mma_bf16(oc[mt][dp * 2 + 1], pa[mt], vf[2], vf[3]);
            }
        }
    }

    // ---- store O bf16 [row][256]
    #pragma unroll
    for (int mt = 0; mt < 4; mt++) {
        const long row = (long)win * 64 + mt * 16 + gid;
        #pragma unroll
        for (int nt = 0; nt < 4; nt++) {
            const int col = head * 32 + nt * 8 + 2 * tig;
            *(uint32_t*)&O[row * 256 + col] =
                packbf(oc[mt][nt][0], oc[mt][nt][1]);
            *(uint32_t*)&O[(row + 8) * 256 + col] =
                packbf(oc[mt][nt][2], oc[mt][nt][3]);
        }
    }
}

// ---------------------------------------------------------------------------
// K5: window reverse + roll(+4,+4) + 2*(attn + x) + transpose to BCHW.
// ---------------------------------------------------------------------------
__global__ void k5_epilogue(const float* __restrict__ P,
                            const float* __restrict__ x,
                            float* __restrict__ out) {
    __shared__ float tile[32][257];
    const int b  = blockIdx.z;
    const int h  = blockIdx.y;
    const int w0 = blockIdx.x * 32;
    const int t  = threadIdx.x;

    const int h2 = (h - 4) & 127;
    #pragma unroll 4
    for (int p2 = 0; p2 < 32; p2++) {
        const int w2 = (w0 + p2 - 4) & 127;
        const long row = (((long)b * 16 + (h2 >> 3)) * 16 + (w2 >> 3)) * 64
                         + (h2 & 7) * 8 + (w2 & 7);
        tile[p2][t] = P[row * Cdim + t];
    }
    __syncthreads();

    const int wl = t & 31;
    const int co = t >> 5;
    const long base = (long)b * Cdim * Hdim * Wdim;
    #pragma unroll
    for (int cb = 0; cb < Cdim; cb += 8) {
        const int c = cb + co;
        const long idx = base + ((long)c * Hdim + h) * Wdim + w0 + wl;
        out[idx] = 2.f * (tile[wl][c] + x[idx]);
    }
}

// ---------------------------------------------------------------------------
extern "C" void kernel_launch(void* const* d_in, const int* in_sizes, int n_in,
                              void* d_out, int out_size) {
    const float* x      = (const float*)d_in[0];
    const float* n1g    = (const float*)d_in[1];
    const float* n1b    = (const float*)d_in[2];
    const float* w_qkv  = (const float*)d_in[3];
    const float* b_qkv  = (const float*)d_in[4];
    const float* w_proj = (const float*)d_in[5];
    const float* b_proj = (const float*)d_in[6];
    float* out = (float*)d_out;

    __nv_bfloat16 *Y, *QKV, *Obuf, *WTq, *WTp;
    float *P;
    cudaGetSymbolAddress((void**)&Y,    g_Y);
    cudaGetSymbolAddress((void**)&QKV,  g_QKV);
    cudaGetSymbolAddress((void**)&Obuf, g_O);
    cudaGetSymbolAddress((void**)&P,    g_P);
    cudaGetSymbolAddress((void**)&WTq,  g_WTq);
    cudaGetSymbolAddress((void**)&WTp,  g_WTp);

    const int att_smem = 3 * 8 * 64 * AP * 2;  // 122880 B
    cudaFuncSetAttribute(k3_attention,
                         cudaFuncAttributeMaxDynamicSharedMemorySize, att_smem);

    // W0: weight transpose+convert
    wconv<<<768, 256>>>(w_qkv, w_proj);

    // K1: LN + shift + window partition -> bf16
    k1_ln_roll_part<<<dim3(4, 128, 8), 256>>>(x, n1g, n1b, Y);

    // K2: QKV GEMM (bf16 tensor cores), output bf16
    bf16_gemm<true><<<dim3(6, 1024), 256>>>(Y, WTq, b_qkv, QKV, 768);

    // K3: tensor-core windowed attention
    k3_attention<<<2048, 256, att_smem>>>(QKV, Obuf);

    // K4: proj GEMM, output fp32
    bf16_gemm<false><<<dim3(2, 1024), 256>>>(Obuf, WTp, b_proj, P, 256);

    // K5: reverse + unshift + 2*(attn + x) -> BCHW
    k5_epilogue<<<dim3(4, 128, 8), 256>>>(P, x, out);
}

// round 5
// speedup vs baseline: 4.5012x; 1.0605x over previous
#include <cuda_runtime.h>
#include <cuda_bf16.h>
#include <cstdint>

// ---------------------------------------------------------------------------
// SwinBasicBlock: out = 2 * (window_attention(LN(x)) + x), BCHW.
// MLP branch is dead code in the reference -> skipped.
// B=8, C=256, H=W=128, WS=8, NH=8, hd=32, SHIFT=4, M = 131072 rows.
// ---------------------------------------------------------------------------

#define Cdim 256
#define Hdim 128
#define Wdim 128
#define MROWS 131072

// Scratch (device globals; allocation APIs forbidden)
__device__ __nv_bfloat16 g_Y[MROWS * Cdim];       // LN output, bf16
__device__ __nv_bfloat16 g_QKV[MROWS * 3 * Cdim]; // qkv, bf16
__device__ __nv_bfloat16 g_O[MROWS * Cdim];       // attn out, bf16
__device__ __nv_bfloat16 g_WTq[768 * 256];        // w_qkv^T  [n][k]
__device__ __nv_bfloat16 g_WTp[256 * 256];        // w_proj^T [n][k]

// ------------------------------ PTX helpers --------------------------------
__device__ __forceinline__ void cp16(uint32_t dst, const void* src) {
    asm volatile("cp.async.cg.shared.global [%0], [%1], 16;\n"
                 :: "r"(dst), "l"(src));
}
__device__ __forceinline__ void cp_commit() {
    asm volatile("cp.async.commit_group;\n");
}
template <int N> __device__ __forceinline__ void cp_wait() {
    asm volatile("cp.async.wait_group %0;\n" :: "n"(N));
}
__device__ __forceinline__ void ldsm_x4(uint32_t r[4], uint32_t addr) {
    asm volatile("ldmatrix.sync.aligned.m8n8.x4.shared.b16 {%0,%1,%2,%3}, [%4];\n"
                 : "=r"(r[0]), "=r"(r[1]), "=r"(r[2]), "=r"(r[3]) : "r"(addr));
}
__device__ __forceinline__ void ldsm_x4_t(uint32_t r[4], uint32_t addr) {
    asm volatile("ldmatrix.sync.aligned.m8n8.x4.trans.shared.b16 {%0,%1,%2,%3}, [%4];\n"
                 : "=r"(r[0]), "=r"(r[1]), "=r"(r[2]), "=r"(r[3]) : "r"(addr));
}
__device__ __forceinline__ void mma_bf16(float c[4], const uint32_t a[4],
                                         uint32_t b0, uint32_t b1) {
    asm volatile(
        "mma.sync.aligned.m16n8k16.row.col.f32.bf16.bf16.f32 "
        "{%0,%1,%2,%3},{%4,%5,%6,%7},{%8,%9},{%0,%1,%2,%3};\n"
        : "+f"(c[0]), "+f"(c[1]), "+f"(c[2]), "+f"(c[3])
        : "r"(a[0]), "r"(a[1]), "r"(a[2]), "r"(a[3]), "r"(b0), "r"(b1));
}
__device__ __forceinline__ uint32_t packbf(float lo, float hi) {
    uint32_t r;
    asm("cvt.rn.bf16x2.f32 %0, %1, %2;\n" : "=r"(r) : "f"(hi), "f"(lo));
    return r;
}
__device__ __forceinline__ uint32_t s2u(const void* p) {
    return (uint32_t)__cvta_generic_to_shared(p);
}

// ---------------------------------------------------------------------------
// W0: transpose weights to [N][K] bf16.
// ---------------------------------------------------------------------------
__global__ void wconv(const float* __restrict__ wq, const float* __restrict__ wp) {
    const int idx = blockIdx.x * 256 + threadIdx.x;   // 768*256 threads
    const int n = idx >> 8, k = idx & 255;
    g_WTq[idx] = __float2bfloat16(wq[k * 768 + n]);
    if (n < 256) g_WTp[idx] = __float2bfloat16(wp[k * 256 + n]);
}

// ---------------------------------------------------------------------------
// K1: LayerNorm over C + cyclic shift (-4,-4) + window partition -> bf16 Y.
// ---------------------------------------------------------------------------
__global__ void k1_ln_roll_part(const float* __restrict__ x,
                                const float* __restrict__ gamma,
                                const float* __restrict__ beta,
                                __nv_bfloat16* __restrict__ Y) {
    __shared__ float tile[32][257];
    const int b  = blockIdx.z;
    const int h  = blockIdx.y;
    const int w0 = blockIdx.x * 32;
    const int t  = threadIdx.x;
    const int wl = t & 31;
    const int co = t >> 5;

    const float* xb = x + (long)b * Cdim * Hdim * Wdim;
    #pragma unroll
    for (int cb = 0; cb < Cdim; cb += 8) {
        const int c = cb + co;
        tile[wl][c] = xb[((long)c * Hdim + h) * Wdim + w0 + wl];
    }
    __syncthreads();

    const int p = t >> 3, sub = t & 7;
    float s = 0.f, ss = 0.f;
    #pragma unroll
    for (int c = sub; c < Cdim; c += 8) {
        const float v = tile[p][c];
        s += v; ss += v * v;
    }
    #pragma unroll
    for (int off = 4; off > 0; off >>= 1) {
        s  += __shfl_xor_sync(0xffffffffu, s,  off);
        ss += __shfl_xor_sync(0xffffffffu, ss, off);
    }
    const float mean = s * (1.f / Cdim);
    const float var  = ss * (1.f / Cdim) - mean * mean;
    const float inv  = rsqrtf(var + 1e-5f);
    #pragma unroll
    for (int c = sub; c < Cdim; c += 8)
        tile[p][c] = (tile[p][c] - mean) * inv * gamma[c] + beta[c];
    __syncthreads();

    const int h2 = (h - 4) & 127;
    #pragma unroll 4
    for (int p2 = 0; p2 < 32; p2++) {
        const int w2 = (w0 + p2 - 4) & 127;
        const long row = (((long)b * 16 + (h2 >> 3)) * 16 + (w2 >> 3)) * 64
                         + (h2 & 7) * 8 + (w2 & 7);
        Y[row * Cdim + t] = __float2bfloat16(tile[p2][t]);
    }
}

// ---------------------------------------------------------------------------
// K2: bf16 tensor-core GEMM: C[M,N] = A[M,256] @ WT[N][256]^T + bias -> bf16.
// Block 128x128, BK=32, 8 warps, warp tile 64x32, cp.async double buffer.
// ---------------------------------------------------------------------------
#define GP 40   // smem row pitch in halves (80 B: 16B-aligned, conflict-free)

__global__ __launch_bounds__(256)
void bf16_gemm_qkv(const __nv_bfloat16* __restrict__ A,
                   const __nv_bfloat16* __restrict__ WT,
                   const float* __restrict__ bias,
                   __nv_bfloat16* __restrict__ Cb, int N) {
    __shared__ __nv_bfloat16 As[2][128 * GP];
    __shared__ __nv_bfloat16 Bs[2][128 * GP];
    const int K = 256;

    const int t    = threadIdx.x;
    const int warp = t >> 5;
    const int lane = t & 31;
    const int gid  = lane >> 2;
    const int tig  = lane & 3;
    const int wm   = (warp >> 2) * 64;
    const int wn   = (warp & 3) * 32;
    const int bm   = blockIdx.y * 128;
    const int bn   = blockIdx.x * 128;

    const uint32_t asb = s2u(&As[0][0]);
    const uint32_t bsb = s2u(&Bs[0][0]);

    auto loadStage = [&](int st, int k0) {
        #pragma unroll
        for (int i = 0; i < 2; i++) {
            const int ci  = t + i * 256;
            const int row = ci >> 2;
            const int kc  = (ci & 3) * 8;
            cp16(asb + (st * 128 * GP + row * GP + kc) * 2,
                 A + (long)(bm + row) * K + k0 + kc);
            cp16(bsb + (st * 128 * GP + row * GP + kc) * 2,
                 WT + (long)(bn + row) * K + k0 + kc);
        }
        cp_commit();
    };

    float acc[4][4][4];
    #pragma unroll
    for (int i = 0; i < 4; i++)
        #pragma unroll
        for (int j = 0; j < 4; j++)
            #pragma unroll
            for (int r = 0; r < 4; r++) acc[i][j][r] = 0.f;

    loadStage(0, 0);

    const int r16  = lane & 15;
    const int hsel = (lane >> 4) << 3;
    const int sel  = lane >> 3, l8 = lane & 7;

    #pragma unroll 1
    for (int kt = 0; kt < 8; kt++) {
        cp_wait<0>();
        __syncthreads();
        if (kt + 1 < 8) loadStage((kt + 1) & 1, (kt + 1) * 32);

        const int st = kt & 1;
        #pragma unroll
        for (int ks = 0; ks < 2; ks++) {
            uint32_t af[4][4];
            #pragma unroll
            for (int mt = 0; mt < 4; mt++)
                ldsm_x4(af[mt], asb + (st * 128 * GP
                        + (wm + mt * 16 + r16) * GP + ks * 16 + hsel) * 2);
            #pragma unroll
            for (int np = 0; np < 2; np++) {
                const int brow = wn + np * 16 + ((sel & 2) ? 8 : 0) + l8;
                const int bcol = ks * 16 + ((sel & 1) ? 8 : 0);
                uint32_t bf[4];
                ldsm_x4(bf, bsb + (st * 128 * GP + brow * GP + bcol) * 2);
                #pragma unroll
                for (int mt = 0; mt < 4; mt++) {
                    mma_bf16(acc[mt][np * 2],     af[mt], bf[0], bf[1]);
                    mma_bf16(acc[mt][np * 2 + 1], af[mt], bf[2], bf[3]);
                }
            }
        }
        __syncthreads();
    }

    #pragma unroll
    for (int nt = 0; nt < 4; nt++) {
        const int col = bn + wn + nt * 8 + 2 * tig;
        const float b0 = bias[col], b1 = bias[col + 1];
        #pragma unroll
        for (int mt = 0; mt < 4; mt++) {
            const long row = bm + wm + mt * 16 + gid;
            *(uint32_t*)&Cb[row * N + col] =
                packbf(acc[mt][nt][0] + b0, acc[mt][nt][1] + b1);
            *(uint32_t*)&Cb[(row + 8) * N + col] =
                packbf(acc[mt][nt][2] + b0, acc[mt][nt][3] + b1);
        }
    }
}

// ---------------------------------------------------------------------------
// K4E: proj GEMM fused with epilogue: out[b,c,h,w] = 2*(P + x) directly in
// BCHW with window-reverse + roll(+4,+4). P = O @ w_proj^T + bias.
// ---------------------------------------------------------------------------
__global__ __launch_bounds__(256)
void bf16_gemm_proj_epi(const __nv_bfloat16* __restrict__ A,
                        const __nv_bfloat16* __restrict__ WT,
                        const float* __restrict__ bias,
                        const float* __restrict__ x,
                        float* __restrict__ out) {
    __shared__ __nv_bfloat16 As[2][128 * GP];
    __shared__ __nv_bfloat16 Bs[2][128 * GP];
    const int K = 256;

    const int t    = threadIdx.x;
    const int warp = t >> 5;
    const int lane = t & 31;
    const int gid  = lane >> 2;
    const int tig  = lane & 3;
    const int wm   = (warp >> 2) * 64;
    const int wn   = (warp & 3) * 32;
    const int bm   = blockIdx.y * 128;
    const int bn   = blockIdx.x * 128;

    const uint32_t asb = s2u(&As[0][0]);
    const uint32_t bsb = s2u(&Bs[0][0]);

    auto loadStage = [&](int st, int k0) {
        #pragma unroll
        for (int i = 0; i < 2; i++) {
            const int ci  = t + i * 256;
            const int row = ci >> 2;
            const int kc  = (ci & 3) * 8;
            cp16(asb + (st * 128 * GP + row * GP + kc) * 2,
                 A + (long)(bm + row) * K + k0 + kc);
            cp16(bsb + (st * 128 * GP + row * GP + kc) * 2,
                 WT + (long)(bn + row) * K + k0 + kc);
        }
        cp_commit();
    };

    float acc[4][4][4];
    #pragma unroll
    for (int i = 0; i < 4; i++)
        #pragma unroll
        for (int j = 0; j < 4; j++)
            #pragma unroll
            for (int r = 0; r < 4; r++) acc[i][j][r] = 0.f;

    loadStage(0, 0);

    const int r16  = lane & 15;
    const int hsel = (lane >> 4) << 3;
    const int sel  = lane >> 3, l8 = lane & 7;

    #pragma unroll 1
    for (int kt = 0; kt < 8; kt++) {
        cp_wait<0>();
        __syncthreads();
        if (kt + 1 < 8) loadStage((kt + 1) & 1, (kt + 1) * 32);

        const int st = kt & 1;
        #pragma unroll
        for (int ks = 0; ks < 2; ks++) {
            uint32_t af[4][4];
            #pragma unroll
            for (int mt = 0; mt < 4; mt++)
                ldsm_x4(af[mt], asb + (st * 128 * GP
                        + (wm + mt * 16 + r16) * GP + ks * 16 + hsel) * 2);
            #pragma unroll
            for (int np = 0; np < 2; np++) {
                const int brow = wn + np * 16 + ((sel & 2) ? 8 : 0) + l8;
                const int bcol = ks * 16 + ((sel & 1) ? 8 : 0);
                uint32_t bf[4];
                ldsm_x4(bf, bsb + (st * 128 * GP + brow * GP + bcol) * 2);
                #pragma unroll
                for (int mt = 0; mt < 4; mt++) {
                    mma_bf16(acc[mt][np * 2],     af[mt], bf[0], bf[1]);
                    mma_bf16(acc[mt][np * 2 + 1], af[mt], bf[2], bf[3]);
                }
            }
        }
        __syncthreads();
    }

    // fused epilogue: window-reverse + roll + residual, scattered to BCHW
    #pragma unroll
    for (int mt = 0; mt < 4; mt++) {
        #pragma unroll
        for (int rh = 0; rh < 2; rh++) {
            const int row = bm + wm + mt * 16 + gid + rh * 8;
            const int win = row >> 6;
            const int n   = row & 63;
            const int b   = win >> 8;
            const int wh  = (win >> 4) & 15;
            const int ww  = win & 15;
            const int h   = (wh * 8 + (n >> 3) + 4) & 127;
            const int w   = (ww * 8 + (n & 7) + 4) & 127;
            const long pbase = ((long)b * Cdim) * (Hdim * Wdim) + h * Wdim + w;
            #pragma unroll
            for (int nt = 0; nt < 4; nt++) {
                const int c0 = bn + wn + nt * 8 + 2 * tig;
                const long i0 = pbase + (long)c0 * (Hdim * Wdim);
                const long i1 = i0 + (Hdim * Wdim);
                out[i0] = 2.f * (acc[mt][nt][rh * 2]     + bias[c0]     + x[i0]);
                out[i1] = 2.f * (acc[mt][nt][rh * 2 + 1] + bias[c0 + 1] + x[i1]);
            }
        }
    }
}

// ---------------------------------------------------------------------------
// K3: tensor-core windowed attention. 1 window/block, 512 threads,
// 2 warps per head (each owns 32 of 64 rows). Pitch-40 smem (122.9 KB).
// ---------------------------------------------------------------------------
#define AP 40
#define HTILE (64 * AP)   // halves per (matrix, head)

__global__ __launch_bounds__(512)
void k3_attention(const __nv_bfloat16* __restrict__ QKV,
                  __nv_bfloat16* __restrict__ O) {
    extern __shared__ __nv_bfloat16 smem[];
    const int win   = blockIdx.x;
    const int t     = threadIdx.x;
    const int wid   = t >> 5;
    const int head  = wid >> 1;
    const int mhalf = wid & 1;      // rows [mhalf*32, mhalf*32+32)
    const int lane  = t & 31;
    const int gid   = lane >> 2;
    const int tig   = lane & 3;

    const uint32_t sb = s2u(smem);

    // cooperative load of the whole window slice (64 x 768 bf16 = 96KB)
    {
        const __nv_bfloat16* src = QKV + (long)win * 64 * 768;
        #pragma unroll
        for (int i = 0; i < 12; i++) {
            const int ci    = i * 512 + t;          // 0..6143 (16B chunks)
            const int token = ci / 96;
            const int c2    = ci % 96;
            const int qkv   = c2 >> 5;
            const int rest  = c2 & 31;
            const int hh    = rest >> 2;
            const int kc    = (rest & 3) * 8;
            cp16(sb + ((qkv * 8 + hh) * HTILE + token * AP + kc) * 2,
                 src + (long)token * 768 + qkv * 256 + hh * 32 + kc);
        }
        cp_commit();
        cp_wait<0>();
        __syncthreads();
    }

    const uint32_t qb = sb + (head * HTILE) * 2;
    const uint32_t kb = sb + ((8 + head) * HTILE) * 2;
    const uint32_t vb = sb + ((16 + head) * HTILE) * 2;

    const int r16  = lane & 15;
    const int hsel = (lane >> 4) << 3;
    const int sel  = lane >> 3, l8 = lane & 7;
    const int mb   = mhalf * 32;

    // ---- S = Q K^T (32x64 rows for this warp), fp32 accum
    float sc[2][8][4];
    #pragma unroll
    for (int mt = 0; mt < 2; mt++)
        #pragma unroll
        for (int nt = 0; nt < 8; nt++)
            #pragma unroll
            for (int r = 0; r < 4; r++) sc[mt][nt][r] = 0.f;

    #pragma unroll
    for (int ks = 0; ks < 2; ks++) {
        uint32_t af[2][4];
        #pragma unroll
        for (int mt = 0; mt < 2; mt++)
            ldsm_x4(af[mt], qb + ((mb + mt * 16 + r16) * AP + ks * 16 + hsel) * 2);
        #pragma unroll
        for (int np = 0; np < 4; np++) {
            const int brow = np * 16 + ((sel & 2) ? 8 : 0) + l8;
            const int bcol = ks * 16 + ((sel & 1) ? 8 : 0);
            uint32_t bf[4];
            ldsm_x4(bf, kb + (brow * AP + bcol) * 2);
            #pragma unroll
            for (int mt = 0; mt < 2; mt++) {
                mma_bf16(sc[mt][np * 2],     af[mt], bf[0], bf[1]);
                mma_bf16(sc[mt][np * 2 + 1], af[mt], bf[2], bf[3]);
            }
        }
    }

    // ---- softmax over rows (quad shuffles)
    const float scale = 0.17677669529663689f;
    float ilo[2], ihi[2];
    #pragma unroll
    for (int mt = 0; mt < 2; mt++) {
        float mlo = -1e30f, mhi = -1e30f;
        #pragma unroll
        for (int nt = 0; nt < 8; nt++) {
            mlo = fmaxf(mlo, fmaxf(sc[mt][nt][0], sc[mt][nt][1]));
            mhi = fmaxf(mhi, fmaxf(sc[mt][nt][2], sc[mt][nt][3]));
        }
        mlo = fmaxf(mlo, __shfl_xor_sync(0xffffffffu, mlo, 1));
        mlo = fmaxf(mlo, __shfl_xor_sync(0xffffffffu, mlo, 2));
        mhi = fmaxf(mhi, __shfl_xor_sync(0xffffffffu, mhi, 1));
        mhi = fmaxf(mhi, __shfl_xor_sync(0xffffffffu, mhi, 2));
        float slo = 0.f, shi = 0.f;
        #pragma unroll
        for (int nt = 0; nt < 8; nt++) {
            sc[mt][nt][0] = __expf(scale * (sc[mt][nt][0] - mlo));
            sc[mt][nt][1] = __expf(scale * (sc[mt][nt][1] - mlo));
            sc[mt][nt][2] = __expf(scale * (sc[mt][nt][2] - mhi));
            sc[mt][nt][3] = __expf(scale * (sc[mt][nt][3] - mhi));
            slo += sc[mt][nt][0] + sc[mt][nt][1];
            shi += sc[mt][nt][2] + sc[mt][nt][3];
        }
        slo += __shfl_xor_sync(0xffffffffu, slo, 1);
        slo += __shfl_xor_sync(0xffffffffu, slo, 2);
        shi += __shfl_xor_sync(0xffffffffu, shi, 1);
        shi += __shfl_xor_sync(0xffffffffu, shi, 2);
        ilo[mt] = 1.f / slo;
        ihi[mt] = 1.f / shi;
    }

    // ---- O = P V (32x32 for this warp)
    float oc[2][4][4];
    #pragma unroll
    for (int mt = 0; mt < 2; mt++)
        #pragma unroll
        for (int nt = 0; nt < 4; nt++)
            #pragma unroll
            for (int r = 0; r < 4; r++) oc[mt][nt][r] = 0.f;

    #pragma unroll
    for (int ks = 0; ks < 4; ks++) {   // token chunks of 16
        uint32_t pa[2][4];
        #pragma unroll
        for (int mt = 0; mt < 2; mt++) {
            pa[mt][0] = packbf(sc[mt][2 * ks][0] * ilo[mt], sc[mt][2 * ks][1] * ilo[mt]);
            pa[mt][1] = packbf(sc[mt][2 * ks][2] * ihi[mt], sc[mt][2 * ks][3] * ihi[mt]);
            pa[mt][2] = packbf(sc[mt][2 * ks + 1][0] * ilo[mt], sc[mt][2 * ks + 1][1] * ilo[mt]);
            pa[mt][3] = packbf(sc[mt][2 * ks + 1][2] * ihi[mt], sc[mt][2 * ks + 1][3] * ihi[mt]);
        }
        #pragma unroll
        for (int dp = 0; dp < 2; dp++) {  // dim chunks of 16
            const int vrow = ks * 16 + ((sel & 1) ? 8 : 0) + l8;
            const int vcol = dp * 16 + ((sel & 2) ? 8 : 0);
            uint32_t vf[4];
            ldsm_x4_t(vf, vb + (vrow * AP + vcol) * 2);
            #pragma unroll
            for (int mt = 0; mt < 2; mt++) {
                mma_bf16(oc[mt][dp * 2],     pa[mt], vf[0], vf[1]);
                mma_bf16(oc[mt][dp * 2 + 1], pa[mt], vf[2], vf[3]);
            }
        }
    }

    // ---- store O bf16 [row][256]
    #pragma unroll
    for (int mt = 0; mt < 2; mt++) {
        const long row = (long)win * 64 + mb + mt * 16 + gid;
        #pragma unroll
        for (int nt = 0; nt < 4; nt++) {
            const int col = head * 32 + nt * 8 + 2 * tig;
            *(uint32_t*)&O[row * 256 + col] =
                packbf(oc[mt][nt][0], oc[mt][nt][1]);
            *(uint32_t*)&O[(row + 8) * 256 + col] =
                packbf(oc[mt][nt][2], oc[mt][nt][3]);
        }
    }
}

// ---------------------------------------------------------------------------
extern "C" void kernel_launch(void* const* d_in, const int* in_sizes, int n_in,
                              void* d_out, int out_size) {
    const float* x      = (const float*)d_in[0];
    const float* n1g    = (const float*)d_in[1];
    const float* n1b    = (const float*)d_in[2];
    const float* w_qkv  = (const float*)d_in[3];
    const float* b_qkv  = (const float*)d_in[4];
    const float* w_proj = (const float*)d_in[5];
    const float* b_proj = (const float*)d_in[6];
    float* out = (float*)d_out;

    __nv_bfloat16 *Y, *QKV, *Obuf, *WTq, *WTp;
    cudaGetSymbolAddress((void**)&Y,    g_Y);
    cudaGetSymbolAddress((void**)&QKV,  g_QKV);
    cudaGetSymbolAddress((void**)&Obuf, g_O);
    cudaGetSymbolAddress((void**)&WTq,  g_WTq);
    cudaGetSymbolAddress((void**)&WTp,  g_WTp);

    const int att_smem = 3 * 8 * 64 * AP * 2;  // 122880 B
    cudaFuncSetAttribute(k3_attention,
                         cudaFuncAttributeMaxDynamicSharedMemorySize, att_smem);

    // W0: weight transpose+convert
    wconv<<<768, 256>>>(w_qkv, w_proj);

    // K1: LN + shift + window partition -> bf16
    k1_ln_roll_part<<<dim3(4, 128, 8), 256>>>(x, n1g, n1b, Y);

    // K2: QKV GEMM (bf16 tensor cores)
    bf16_gemm_qkv<<<dim3(6, 1024), 256>>>(Y, WTq, b_qkv, QKV, 768);

    // K3: tensor-core windowed attention (512 thr, 2 warps/head)
    k3_attention<<<2048, 512, att_smem>>>(QKV, Obuf);

    // K4E: proj GEMM + fused reverse/roll/residual epilogue -> BCHW out
    bf16_gemm_proj_epi<<<dim3(2, 1024), 256>>>(Obuf, WTp, b_proj, x, out);
}